// round 1
// baseline (speedup 1.0000x reference)
#include <cuda_runtime.h>
#include <cstdint>
#include <cstddef>

// ---------------------------------------------------------------------------
// baseline_lstm: encoder folded into LSTM input weights; batch-partitioned
// bidirectional LSTM with no inter-CTA sync; packed f32x2 FMA inner loop.
//
//   gates = c_t @ (W_ih @ W_enc)^T + h_{t-1} @ W_hh^T + (b + W_ih @ b_enc)
//
// 512 independent sequences (256 batch x 2 dirs), 4 per CTA, 128 CTAs.
// ---------------------------------------------------------------------------

#define T_STEPS 4096
#define B_TOT   256
#define HID     64
#define KIN     60          // raw input features (encoder folded away)
#define KTOT    124         // 60 input + 64 hidden
#define NCHUNK  31          // KTOT / 4
#define NGATES  256         // 4 * HID

// __device__ scratch (allocation-free rule: static device globals)
__device__ float g_Wcomb[2][NGATES][KTOT];   // [dir][gate_row][k]  (k<60: input, k>=60: W_hh)
__device__ float g_biasc[2][NGATES];         // combined bias
__device__ float g_cfin[2][B_TOT][HID];      // final cell states

__device__ __forceinline__ unsigned long long pack2(float lo, float hi) {
    unsigned long long u;
    asm("mov.b64 %0, {%1, %2};" : "=l"(u) : "f"(lo), "f"(hi));
    return u;
}
__device__ __forceinline__ void unpack2(unsigned long long u, float& lo, float& hi) {
    asm("mov.b64 {%0, %1}, %2;" : "=f"(lo), "=f"(hi) : "l"(u));
}
// packed dual FMA: d.lo += a.lo*b.lo ; d.hi += a.hi*b.hi   (FFMA2 in SASS)
__device__ __forceinline__ void ffma2(unsigned long long& d,
                                      unsigned long long a,
                                      unsigned long long b) {
    asm("fma.rn.f32x2 %0, %1, %2, %0;" : "+l"(d) : "l"(a), "l"(b));
}

__device__ __forceinline__ float fast_sigmoid(float x) {
    return __fdividef(1.0f, 1.0f + __expf(-x));
}
__device__ __forceinline__ float fast_tanh(float x) {
    // 1 - 2/(e^{2x}+1); correct saturation at +/-inf via IEEE semantics
    return 1.0f - __fdividef(2.0f, __expf(2.0f * x) + 1.0f);
}

// ---------------------------------------------------------------------------
// Prep: fold encoder into LSTM input weights.
//   Wcomb[dir][r][k<60]  = sum_e W_ih[r][e] * W_enc[e][k]
//   Wcomb[dir][r][60+k]  = W_hh[r][k]
//   biasc[dir][r]        = b[r] + sum_e W_ih[r][e] * b_enc[e]
// grid = 2 blocks (dir), 256 threads (gate row)
// ---------------------------------------------------------------------------
__global__ void prep_kernel(const float* __restrict__ W_enc,
                            const float* __restrict__ b_enc,
                            const float* __restrict__ W_ih_f,
                            const float* __restrict__ W_hh_f,
                            const float* __restrict__ b_f,
                            const float* __restrict__ W_ih_b,
                            const float* __restrict__ W_hh_b,
                            const float* __restrict__ b_b) {
    const int dir = blockIdx.x;
    const int r   = threadIdx.x;
    const float* W_ih = dir ? W_ih_b : W_ih_f;
    const float* W_hh = dir ? W_hh_b : W_hh_f;
    const float* bv   = dir ? b_b    : b_f;

    float wih[32];
#pragma unroll
    for (int e = 0; e < 32; e++) wih[e] = W_ih[r * 32 + e];

    for (int k = 0; k < KIN; k++) {
        float s = 0.0f;
#pragma unroll
        for (int e = 0; e < 32; e++) s += wih[e] * W_enc[e * 60 + k];
        g_Wcomb[dir][r][k] = s;
    }
#pragma unroll
    for (int k = 0; k < HID; k++) g_Wcomb[dir][r][KIN + k] = W_hh[r * HID + k];

    float s = bv[r];
#pragma unroll
    for (int e = 0; e < 32; e++) s += wih[e] * b_enc[e];
    g_biasc[dir][r] = s;
}

// ---------------------------------------------------------------------------
// Recurrent kernel: 128 CTAs x 256 threads. CTA = (dir, 4 batch seqs).
// Thread = one gate row (owns 124 weights as 62 packed u64 regs).
// Per step: 4 seqs x 62 FFMA2, gate transpose via smem, LSTM epilogue.
// ---------------------------------------------------------------------------
__global__ void __launch_bounds__(256, 1)
lstm_kernel(const float* __restrict__ cin) {
    const int dir = blockIdx.x >> 6;     // 0..1
    const int bg  = blockIdx.x & 63;     // batch group of 4
    const int tid = threadIdx.x;         // gate row 0..255

    __shared__ __align__(16) float buf[4][128];  // per seq: [0:60)=x_t, [60:124)=h
    __shared__ float gsm[4][NGATES];             // gate transpose buffer

    // load combined weights into registers as packed (k, k+1) pairs
    unsigned long long wv[62];
    {
        const float* wr = &g_Wcomb[dir][tid][0];
#pragma unroll
        for (int p = 0; p < 62; p++) {
            float2 w = *reinterpret_cast<const float2*>(wr + 2 * p);
            wv[p] = pack2(w.x, w.y);
        }
    }
    const float bias = g_biasc[dir][tid];
    const unsigned long long acc_init = pack2(bias, 0.0f);

    // zero hidden-state region (h_0 = 0)
    buf[tid >> 6][KIN + (tid & 63)] = 0.0f;

    // x prefetch mapping: threads 0..239 each own one (seq, feature) element
    const int  xs   = tid / KIN;
    const int  xk   = tid - xs * KIN;
    const bool xact = (tid < 4 * KIN);
    const float* cbase = cin + ((size_t)(bg * 4 + xs) * T_STEPS) * KIN + xk;

    if (xact) {
        const int t0 = dir ? (T_STEPS - 1) : 0;
        buf[xs][xk] = cbase[(size_t)t0 * KIN];
    }

    const int s_ep = tid >> 6;   // epilogue: which seq
    const int j_ep = tid & 63;   // epilogue: which hidden unit
    float cst = 0.0f;            // cell state (lives in this thread forever)
    __syncthreads();

    float xnext = 0.0f;
    for (int t = 0; t < T_STEPS; t++) {
        // prefetch next step's input row into registers (hides DRAM latency)
        if (xact && (t + 1) < T_STEPS) {
            const int tp = dir ? (T_STEPS - 2 - t) : (t + 1);
            xnext = __ldg(cbase + (size_t)tp * KIN);
        }

        unsigned long long a0 = acc_init, a1 = acc_init, a2 = acc_init, a3 = acc_init;
#pragma unroll
        for (int ch = 0; ch < NCHUNK; ch++) {
            const ulonglong2 v0 = *reinterpret_cast<const ulonglong2*>(&buf[0][ch * 4]);
            const ulonglong2 v1 = *reinterpret_cast<const ulonglong2*>(&buf[1][ch * 4]);
            const ulonglong2 v2 = *reinterpret_cast<const ulonglong2*>(&buf[2][ch * 4]);
            const ulonglong2 v3 = *reinterpret_cast<const ulonglong2*>(&buf[3][ch * 4]);
            ffma2(a0, wv[2 * ch], v0.x); ffma2(a0, wv[2 * ch + 1], v0.y);
            ffma2(a1, wv[2 * ch], v1.x); ffma2(a1, wv[2 * ch + 1], v1.y);
            ffma2(a2, wv[2 * ch], v2.x); ffma2(a2, wv[2 * ch + 1], v2.y);
            ffma2(a3, wv[2 * ch], v3.x); ffma2(a3, wv[2 * ch + 1], v3.y);
        }
        {
            float lo, hi;
            unpack2(a0, lo, hi); gsm[0][tid] = lo + hi;
            unpack2(a1, lo, hi); gsm[1][tid] = lo + hi;
            unpack2(a2, lo, hi); gsm[2][tid] = lo + hi;
            unpack2(a3, lo, hi); gsm[3][tid] = lo + hi;
        }
        __syncthreads();   // gates ready; buf reads complete

        // LSTM epilogue: thread -> (seq s_ep, hidden unit j_ep)
        const float gi = gsm[s_ep][j_ep];
        const float gf = gsm[s_ep][HID + j_ep];
        const float gg = gsm[s_ep][2 * HID + j_ep];
        const float go = gsm[s_ep][3 * HID + j_ep];

        const float ig = fast_sigmoid(gi);
        const float fg = fast_sigmoid(gf);
        const float og = fast_sigmoid(go);
        const float gt = fast_tanh(gg);

        cst = fg * cst + ig * gt;
        const float hv = og * fast_tanh(cst);

        buf[s_ep][KIN + j_ep] = hv;                       // publish h_t
        if (xact && (t + 1) < T_STEPS) buf[xs][xk] = xnext;  // publish x_{t+1}
        __syncthreads();   // buf ready for next step
    }

    g_cfin[dir][bg * 4 + s_ep][j_ep] = cst;
}

// ---------------------------------------------------------------------------
// Final FC: out[b] = W_fin @ concat(c_fwd[b], c_bwd[b]) + b_fin
// ---------------------------------------------------------------------------
__global__ void final_kernel(const float* __restrict__ W_fin,
                             const float* __restrict__ b_fin,
                             float* __restrict__ out) {
    const int b = threadIdx.x;  // 0..255
    float a0 = b_fin[0], a1 = b_fin[1], a2 = b_fin[2];
#pragma unroll
    for (int j = 0; j < HID; j++) {
        const float cf = g_cfin[0][b][j];
        a0 += W_fin[0 * 128 + j] * cf;
        a1 += W_fin[1 * 128 + j] * cf;
        a2 += W_fin[2 * 128 + j] * cf;
    }
#pragma unroll
    for (int j = 0; j < HID; j++) {
        const float cb = g_cfin[1][b][j];
        a0 += W_fin[0 * 128 + 64 + j] * cb;
        a1 += W_fin[1 * 128 + 64 + j] * cb;
        a2 += W_fin[2 * 128 + 64 + j] * cb;
    }
    out[b * 3 + 0] = a0;
    out[b * 3 + 1] = a1;
    out[b * 3 + 2] = a2;
}

extern "C" void kernel_launch(void* const* d_in, const int* in_sizes, int n_in,
                              void* d_out, int out_size) {
    (void)in_sizes; (void)n_in; (void)out_size;
    const float* c      = (const float*)d_in[0];
    const float* W_enc  = (const float*)d_in[1];
    const float* b_enc  = (const float*)d_in[2];
    const float* W_ih_f = (const float*)d_in[3];
    const float* W_hh_f = (const float*)d_in[4];
    const float* b_f    = (const float*)d_in[5];
    const float* W_ih_b = (const float*)d_in[6];
    const float* W_hh_b = (const float*)d_in[7];
    const float* b_b    = (const float*)d_in[8];
    const float* W_fin  = (const float*)d_in[9];
    const float* b_fin  = (const float*)d_in[10];
    float* out = (float*)d_out;

    prep_kernel<<<2, 256>>>(W_enc, b_enc, W_ih_f, W_hh_f, b_f, W_ih_b, W_hh_b, b_b);
    lstm_kernel<<<128, 256>>>(c);
    final_kernel<<<1, 256>>>(W_fin, b_fin, out);
}

// round 2
// speedup vs baseline: 1.4636x; 1.4636x over previous
#include <cuda_runtime.h>
#include <cstdint>
#include <cstddef>

// ---------------------------------------------------------------------------
// Bidirectional LSTM, encoder folded into input weights.
// 512 independent sequences (256 batch x 2 dirs), 4 per CTA, 128 CTAs.
//
// Round 2 restructure: thread = (2 gate rows) x (64-k half). Each broadcast
// LDS.128 feeds 4 FFMA2 (was 2), halving LDS issue pressure that was
// co-saturating with the FMA pipe. Gate = sum of 2 k-half partials (smem).
// ---------------------------------------------------------------------------

#define T_STEPS 4096
#define B_TOT   256
#define HID     64
#define KIN     60
#define KPAD    128          // 60 input + 64 hidden + 4 zero pad
#define NGATES  256

__device__ float g_Wcomb[2][NGATES][KPAD];   // [dir][gate_row][k] (padded, k>=124 zero)
__device__ float g_biasc[2][NGATES];
__device__ float g_cfin[2][B_TOT][HID];

__device__ __forceinline__ unsigned long long pack2(float lo, float hi) {
    unsigned long long u;
    asm("mov.b64 %0, {%1, %2};" : "=l"(u) : "f"(lo), "f"(hi));
    return u;
}
__device__ __forceinline__ void unpack2(unsigned long long u, float& lo, float& hi) {
    asm("mov.b64 {%0, %1}, %2;" : "=f"(lo), "=f"(hi) : "l"(u));
}
__device__ __forceinline__ void ffma2(unsigned long long& d,
                                      unsigned long long a,
                                      unsigned long long b) {
    asm("fma.rn.f32x2 %0, %1, %2, %0;" : "+l"(d) : "l"(a), "l"(b));
}

__device__ __forceinline__ float fast_sigmoid(float x) {
    return __fdividef(1.0f, 1.0f + __expf(-x));
}
__device__ __forceinline__ float fast_tanh(float x) {
    return 1.0f - __fdividef(2.0f, __expf(2.0f * x) + 1.0f);
}

// ---------------------------------------------------------------------------
__global__ void prep_kernel(const float* __restrict__ W_enc,
                            const float* __restrict__ b_enc,
                            const float* __restrict__ W_ih_f,
                            const float* __restrict__ W_hh_f,
                            const float* __restrict__ b_f,
                            const float* __restrict__ W_ih_b,
                            const float* __restrict__ W_hh_b,
                            const float* __restrict__ b_b) {
    const int dir = blockIdx.x;
    const int r   = threadIdx.x;
    const float* W_ih = dir ? W_ih_b : W_ih_f;
    const float* W_hh = dir ? W_hh_b : W_hh_f;
    const float* bv   = dir ? b_b    : b_f;

    float wih[32];
#pragma unroll
    for (int e = 0; e < 32; e++) wih[e] = W_ih[r * 32 + e];

    for (int k = 0; k < KIN; k++) {
        float s = 0.0f;
#pragma unroll
        for (int e = 0; e < 32; e++) s += wih[e] * W_enc[e * 60 + k];
        g_Wcomb[dir][r][k] = s;
    }
#pragma unroll
    for (int k = 0; k < HID; k++) g_Wcomb[dir][r][KIN + k] = W_hh[r * HID + k];
#pragma unroll
    for (int k = KIN + HID; k < KPAD; k++) g_Wcomb[dir][r][k] = 0.0f;

    float s = bv[r];
#pragma unroll
    for (int e = 0; e < 32; e++) s += wih[e] * b_enc[e];
    g_biasc[dir][r] = s;
}

// dummy pad so ncu -s 5 -c 1 lands on lstm_kernel
__global__ void pad_kernel() {}

// ---------------------------------------------------------------------------
// 128 CTAs x 256 threads. CTA = (dir, 4 batch seqs).
// Thread tid: half = tid>>7 (k in [64h, 64h+64)), pair p = tid&127
//             -> gate rows 2p, 2p+1.
// Per chunk of 4 k's: 1 broadcast LDS.128 per seq feeds 4 FFMA2.
// ---------------------------------------------------------------------------
__global__ void __launch_bounds__(256, 1)
lstm_kernel(const float* __restrict__ cin) {
    const int dir = blockIdx.x >> 6;
    const int bg  = blockIdx.x & 63;
    const int tid = threadIdx.x;

    __shared__ __align__(16) float buf[4][KPAD];        // per seq: x | h | pad
    __shared__ __align__(8)  float part[4][2][NGATES];  // k-half partial gates

    const int half = tid >> 7;        // 0..1
    const int p    = tid & 127;       // row pair
    const int r0   = 2 * p;
    const int k0   = half * 64;

    // weights: 2 rows x 64 k's as packed pairs (128 regs)
    unsigned long long wv0[32], wv1[32];
    {
        const float* wr0 = &g_Wcomb[dir][r0][k0];
        const float* wr1 = &g_Wcomb[dir][r0 + 1][k0];
#pragma unroll
        for (int i = 0; i < 32; i++) {
            float2 a = *reinterpret_cast<const float2*>(wr0 + 2 * i);
            float2 b = *reinterpret_cast<const float2*>(wr1 + 2 * i);
            wv0[i] = pack2(a.x, a.y);
            wv1[i] = pack2(b.x, b.y);
        }
    }
    // bias folded into half-0 accumulator init
    const unsigned long long init0 =
        half ? 0ull : pack2(g_biasc[dir][r0], 0.0f);
    const unsigned long long init1 =
        half ? 0ull : pack2(g_biasc[dir][r0 + 1], 0.0f);

    // zero whole buf (h0 = 0, pad = 0); x written after barrier
    for (int i = tid; i < 4 * KPAD; i += 256)
        (&buf[0][0])[i] = 0.0f;
    __syncthreads();

    // x prefetch mapping: threads 0..239 own one (seq, feature)
    const int  xs   = tid / KIN;
    const int  xk   = tid - xs * KIN;
    const bool xact = (tid < 4 * KIN);
    const float* cbase = cin + ((size_t)(bg * 4 + xs) * T_STEPS) * KIN + xk;

    if (xact) {
        const int t0 = dir ? (T_STEPS - 1) : 0;
        buf[xs][xk] = cbase[(size_t)t0 * KIN];
    }

    const int s_ep = tid >> 6;
    const int j_ep = tid & 63;
    float cst = 0.0f;
    __syncthreads();

    float xnext = 0.0f;
    for (int t = 0; t < T_STEPS; t++) {
        if (xact && (t + 1) < T_STEPS) {
            const int tp = dir ? (T_STEPS - 2 - t) : (t + 1);
            xnext = __ldg(cbase + (size_t)tp * KIN);
        }

        // acc[row][seq]
        unsigned long long a00 = init0, a01 = init0, a02 = init0, a03 = init0;
        unsigned long long a10 = init1, a11 = init1, a12 = init1, a13 = init1;
#pragma unroll
        for (int ch = 0; ch < 16; ch++) {
            const ulonglong2 v0 = *reinterpret_cast<const ulonglong2*>(&buf[0][k0 + 4 * ch]);
            const ulonglong2 v1 = *reinterpret_cast<const ulonglong2*>(&buf[1][k0 + 4 * ch]);
            const ulonglong2 v2 = *reinterpret_cast<const ulonglong2*>(&buf[2][k0 + 4 * ch]);
            const ulonglong2 v3 = *reinterpret_cast<const ulonglong2*>(&buf[3][k0 + 4 * ch]);
            ffma2(a00, wv0[2 * ch], v0.x); ffma2(a00, wv0[2 * ch + 1], v0.y);
            ffma2(a10, wv1[2 * ch], v0.x); ffma2(a10, wv1[2 * ch + 1], v0.y);
            ffma2(a01, wv0[2 * ch], v1.x); ffma2(a01, wv0[2 * ch + 1], v1.y);
            ffma2(a11, wv1[2 * ch], v1.x); ffma2(a11, wv1[2 * ch + 1], v1.y);
            ffma2(a02, wv0[2 * ch], v2.x); ffma2(a02, wv0[2 * ch + 1], v2.y);
            ffma2(a12, wv1[2 * ch], v2.x); ffma2(a12, wv1[2 * ch + 1], v2.y);
            ffma2(a03, wv0[2 * ch], v3.x); ffma2(a03, wv0[2 * ch + 1], v3.y);
            ffma2(a13, wv1[2 * ch], v3.x); ffma2(a13, wv1[2 * ch + 1], v3.y);
        }
        {
            float l0, h0, l1, h1;
            unpack2(a00, l0, h0); unpack2(a10, l1, h1);
            *reinterpret_cast<float2*>(&part[0][half][r0]) = make_float2(l0 + h0, l1 + h1);
            unpack2(a01, l0, h0); unpack2(a11, l1, h1);
            *reinterpret_cast<float2*>(&part[1][half][r0]) = make_float2(l0 + h0, l1 + h1);
            unpack2(a02, l0, h0); unpack2(a12, l1, h1);
            *reinterpret_cast<float2*>(&part[2][half][r0]) = make_float2(l0 + h0, l1 + h1);
            unpack2(a03, l0, h0); unpack2(a13, l1, h1);
            *reinterpret_cast<float2*>(&part[3][half][r0]) = make_float2(l0 + h0, l1 + h1);
        }
        __syncthreads();   // partials ready; buf reads complete

        // epilogue: thread -> (seq s_ep, hidden unit j_ep)
        const float gi = part[s_ep][0][j_ep]           + part[s_ep][1][j_ep];
        const float gf = part[s_ep][0][HID + j_ep]     + part[s_ep][1][HID + j_ep];
        const float gg = part[s_ep][0][2 * HID + j_ep] + part[s_ep][1][2 * HID + j_ep];
        const float go = part[s_ep][0][3 * HID + j_ep] + part[s_ep][1][3 * HID + j_ep];

        const float ig = fast_sigmoid(gi);
        const float fg = fast_sigmoid(gf);
        const float og = fast_sigmoid(go);
        const float gt = fast_tanh(gg);

        cst = fg * cst + ig * gt;
        const float hv = og * fast_tanh(cst);

        buf[s_ep][KIN + j_ep] = hv;
        if (xact && (t + 1) < T_STEPS) buf[xs][xk] = xnext;
        __syncthreads();
    }

    g_cfin[dir][bg * 4 + s_ep][j_ep] = cst;
}

// ---------------------------------------------------------------------------
__global__ void final_kernel(const float* __restrict__ W_fin,
                             const float* __restrict__ b_fin,
                             float* __restrict__ out) {
    const int b = threadIdx.x;
    float a0 = b_fin[0], a1 = b_fin[1], a2 = b_fin[2];
#pragma unroll
    for (int j = 0; j < HID; j++) {
        const float cf = g_cfin[0][b][j];
        a0 += W_fin[0 * 128 + j] * cf;
        a1 += W_fin[1 * 128 + j] * cf;
        a2 += W_fin[2 * 128 + j] * cf;
    }
#pragma unroll
    for (int j = 0; j < HID; j++) {
        const float cb = g_cfin[1][b][j];
        a0 += W_fin[0 * 128 + 64 + j] * cb;
        a1 += W_fin[1 * 128 + 64 + j] * cb;
        a2 += W_fin[2 * 128 + 64 + j] * cb;
    }
    out[b * 3 + 0] = a0;
    out[b * 3 + 1] = a1;
    out[b * 3 + 2] = a2;
}

extern "C" void kernel_launch(void* const* d_in, const int* in_sizes, int n_in,
                              void* d_out, int out_size) {
    (void)in_sizes; (void)n_in; (void)out_size;
    const float* c      = (const float*)d_in[0];
    const float* W_enc  = (const float*)d_in[1];
    const float* b_enc  = (const float*)d_in[2];
    const float* W_ih_f = (const float*)d_in[3];
    const float* W_hh_f = (const float*)d_in[4];
    const float* b_f    = (const float*)d_in[5];
    const float* W_ih_b = (const float*)d_in[6];
    const float* W_hh_b = (const float*)d_in[7];
    const float* b_b    = (const float*)d_in[8];
    const float* W_fin  = (const float*)d_in[9];
    const float* b_fin  = (const float*)d_in[10];
    float* out = (float*)d_out;

    prep_kernel<<<2, 256>>>(W_enc, b_enc, W_ih_f, W_hh_f, b_f, W_ih_b, W_hh_b, b_b);
    // pads: align ncu -s 5 -c 1 onto lstm_kernel
    pad_kernel<<<1, 32>>>();
    pad_kernel<<<1, 32>>>();
    lstm_kernel<<<128, 256>>>(c);
    final_kernel<<<1, 256>>>(W_fin, b_fin, out);
}